// round 2
// baseline (speedup 1.0000x reference)
#include <cuda_runtime.h>
#include <cuda_bf16.h>
#include <cstdint>

// Problem constants
#define B_ 128
#define H_ 512
#define I_ 512
#define SIXH 3072
#define BH (B_ * H_)          // 65536
#define CSZ (B_ * H_ * H_)    // 33554432

// ---------------- scratch (no allocs allowed) ----------------
__device__ float g_gates[B_ * SIXH];   // [b, 6H]
__device__ float g_f[BH];
__device__ float g_add[BH];
__device__ float g_o[BH];
__device__ float g_denom[B_];

// ---------------- Kernel 1: gates = x @ W^T + bias ----------------
// M=128(b), N=3072(gate), K=512. Both operands K-major (NT gemm).
// 64x64 tile, BK=16, 256 threads, 4x4 micro-tile per thread.
#define BM 64
#define BN 64
#define BK 16

__global__ __launch_bounds__(256) void gemm_kernel(
    const float* __restrict__ x,      // [128,512]
    const float* __restrict__ W,      // [3072,512]
    const float* __restrict__ bias)   // [3072]
{
    __shared__ float sA[BK][BM + 4];  // [k][m]
    __shared__ float sB[BK][BN + 4];  // [k][n]

    const int bn = blockIdx.x * BN;
    const int bm = blockIdx.y * BM;
    const int tid = threadIdx.x;
    const int tm = (tid >> 4) * 4;   // 0..60
    const int tn = (tid & 15) * 4;   // 0..60

    float acc[4][4] = {};

    // float4 loader indices: each thread loads one float4 of A and one of B per k-tile
    const int lm = tid >> 2;          // 0..63 row within tile
    const int lk = (tid & 3) * 4;     // 0,4,8,12 k offset

    for (int k0 = 0; k0 < I_; k0 += BK) {
        float4 a4 = *reinterpret_cast<const float4*>(x + (bm + lm) * I_ + k0 + lk);
        float4 b4 = *reinterpret_cast<const float4*>(W + (bn + lm) * I_ + k0 + lk);
        sA[lk + 0][lm] = a4.x; sA[lk + 1][lm] = a4.y; sA[lk + 2][lm] = a4.z; sA[lk + 3][lm] = a4.w;
        sB[lk + 0][lm] = b4.x; sB[lk + 1][lm] = b4.y; sB[lk + 2][lm] = b4.z; sB[lk + 3][lm] = b4.w;
        __syncthreads();

        #pragma unroll
        for (int k = 0; k < BK; k++) {
            float a[4], b[4];
            #pragma unroll
            for (int i = 0; i < 4; i++) a[i] = sA[k][tm + i];
            #pragma unroll
            for (int j = 0; j < 4; j++) b[j] = sB[k][tn + j];
            #pragma unroll
            for (int i = 0; i < 4; i++)
                #pragma unroll
                for (int j = 0; j < 4; j++)
                    acc[i][j] += a[i] * b[j];
        }
        __syncthreads();
    }

    float4 bb = *reinterpret_cast<const float4*>(bias + bn + tn);
    #pragma unroll
    for (int i = 0; i < 4; i++) {
        float4 r;
        r.x = acc[i][0] + bb.x;
        r.y = acc[i][1] + bb.y;
        r.z = acc[i][2] + bb.z;
        r.w = acc[i][3] + bb.w;
        *reinterpret_cast<float4*>(g_gates + (bm + tm + i) * SIXH + bn + tn) = r;
    }
}

// ---------------- Kernel 2: elementwise gate transforms ----------------
// gate order in the 6H dim: ig, fg, og, q, k, v
__global__ __launch_bounds__(256) void gate_kernel(
    const float* __restrict__ m_prev,
    const float* __restrict__ n_prev,
    float* __restrict__ out_m,
    float* __restrict__ out_n)
{
    int idx = blockIdx.x * blockDim.x + threadIdx.x;   // 0..65535
    int b = idx >> 9;
    int h = idx & (H_ - 1);
    const float* g = g_gates + b * SIXH;

    float ig = g[h];
    float fg = g[H_ + h];
    float og = g[2 * H_ + h];
    float kk = g[4 * H_ + h];
    float vv = g[5 * H_ + h];

    float mp = m_prev[idx];
    float mt = fmaxf(fg + mp, ig);
    float it = expf(ig - mt);
    float ft = expf(fg + mp - mt);
    float kt = 0.04419417382415922f * kk;  // 1/sqrt(512)
    float ot = 1.0f / (1.0f + expf(-og));

    out_m[idx] = mt;
    out_n[idx] = ft * n_prev[idx] + it * kt;
    g_f[idx]   = ft;
    g_add[idx] = it * vv * kt;
    g_o[idx]   = ot;
}

// ---------------- Kernel 3: denom[b] = max(|n_t . q|, 1e-6) ----------------
__global__ __launch_bounds__(128) void nq_kernel(const float* __restrict__ n_t)
{
    int b = blockIdx.x;
    const float* q = g_gates + b * SIXH + 3 * H_;
    const float* n = n_t + b * H_;

    float s = 0.f;
    for (int h = threadIdx.x; h < H_; h += 128) s += n[h] * q[h];

    #pragma unroll
    for (int off = 16; off; off >>= 1) s += __shfl_xor_sync(0xffffffffu, s, off);

    __shared__ float red[4];
    int w = threadIdx.x >> 5, lane = threadIdx.x & 31;
    if (lane == 0) red[w] = s;
    __syncthreads();
    if (threadIdx.x == 0) {
        float t = red[0] + red[1] + red[2] + red[3];
        g_denom[b] = fmaxf(fabsf(t), 1e-6f);
    }
}

// ---------------- Kernel 4: C_t update + readout + h_t ----------------
// One warp per (b,i) row of 512 floats; 8 warps per block; q[b] staged in smem.
__global__ __launch_bounds__(256) void cmain_kernel(
    const float* __restrict__ C_prev,
    float* __restrict__ out_C,
    float* __restrict__ out_h)
{
    __shared__ float sq[H_];
    const int b = blockIdx.x >> 6;            // 64 blocks per batch
    const int row0 = (blockIdx.x & 63) * 8;

    const float* q = g_gates + b * SIXH + 3 * H_;
    for (int h = threadIdx.x; h < H_; h += 256) sq[h] = q[h];
    __syncthreads();

    const int w = threadIdx.x >> 5;
    const int lane = threadIdx.x & 31;
    const int i = row0 + w;
    const int bi = b * H_ + i;

    const float f   = g_f[bi];
    const float add = g_add[bi];

    const float4* Cp = reinterpret_cast<const float4*>(C_prev) + (size_t)bi * (H_ / 4);
    float4*       Co = reinterpret_cast<float4*>(out_C)        + (size_t)bi * (H_ / 4);
    const float4* q4 = reinterpret_cast<const float4*>(sq);

    float acc = 0.f;
    #pragma unroll
    for (int t = 0; t < 4; t++) {
        int j4 = lane + t * 32;
        float4 c = Cp[j4];
        float4 r;
        r.x = fmaf(f, c.x, add);
        r.y = fmaf(f, c.y, add);
        r.z = fmaf(f, c.z, add);
        r.w = fmaf(f, c.w, add);
        Co[j4] = r;
        float4 qq = q4[j4];
        acc += r.x * qq.x + r.y * qq.y + r.z * qq.z + r.w * qq.w;
    }

    #pragma unroll
    for (int off = 16; off; off >>= 1) acc += __shfl_xor_sync(0xffffffffu, acc, off);

    if (lane == 0)
        out_h[bi] = g_o[bi] * acc / g_denom[b];
}

// ---------------- launch ----------------
extern "C" void kernel_launch(void* const* d_in, const int* in_sizes, int n_in,
                              void* d_out, int out_size)
{
    const float* x      = (const float*)d_in[0];
    // d_in[1] = h_prev (unused by the reference)
    const float* C_prev = (const float*)d_in[2];
    const float* m_prev = (const float*)d_in[3];
    const float* n_prev = (const float*)d_in[4];
    const float* W      = (const float*)d_in[5];
    const float* bias   = (const float*)d_in[6];

    float* out   = (float*)d_out;
    float* out_h = out;                       // [B,H]
    float* out_C = out + BH;                  // [B,H,H]
    float* out_m = out + BH + CSZ;            // [B,H]
    float* out_n = out + BH + CSZ + BH;       // [B,H]

    dim3 ggrid(SIXH / BN, B_ / BM);           // (48, 2)
    gemm_kernel<<<ggrid, 256>>>(x, W, bias);

    gate_kernel<<<BH / 256, 256>>>(m_prev, n_prev, out_m, out_n);

    nq_kernel<<<B_, 128>>>(out_n);

    cmain_kernel<<<B_ * 64, 256>>>(C_prev, out_C, out_h);
}

// round 3
// speedup vs baseline: 1.2669x; 1.2669x over previous
#include <cuda_runtime.h>
#include <cuda_bf16.h>
#include <cstdint>

// Problem constants
#define B_ 128
#define H_ 512
#define I_ 512
#define SIXH 3072
#define BH (B_ * H_)          // 65536
#define CSZ (B_ * H_ * H_)    // 33554432

// ---------------- scratch (no allocs allowed) ----------------
__device__ float g_part[3][B_ * SIXH];   // split-K partial gates
__device__ float g_f[BH];
__device__ float g_add[BH];
__device__ float g_o[BH];
__device__ float g_q[BH];
__device__ float g_denom[B_];

// ---------------- Kernel 1: partial gates = x @ W^T (split-K=3) ----------------
// M=128(b), N=3072(gate), K=512. NT gemm, both operands K-major.
// 64x64 tile, BK=16, 128 threads, 4x8 micro-tile, reg-prefetch pipeline.
#define GBM 64
#define GBN 64
#define GBK 16

__global__ __launch_bounds__(128) void gemm_kernel(
    const float* __restrict__ x,      // [128,512]
    const float* __restrict__ W)      // [3072,512]
{
    __shared__ float sA[GBK][GBM + 4];  // [k][m]
    __shared__ float sB[GBK][GBN + 4];  // [k][n]

    const int bn = blockIdx.x * GBN;
    const int bm = blockIdx.y * GBM;
    const int z  = blockIdx.z;                 // k-split 0..2
    const int k_lo = z * 176;                  // 0,176,352
    const int k_hi = (z == 2) ? 512 : k_lo + 176;

    const int t  = threadIdx.x;
    // loader: each thread loads 8 contiguous k (2 float4) of one row, for A and B
    const int lm = t >> 1;                     // 0..63
    const int lk = (t & 1) * 8;                // 0 or 8
    // compute: 16 (m) x 8 (n) thread grid, micro-tile 4x8
    const int tm = (t >> 3) * 4;               // 0..60
    const int tn = (t & 7) * 8;                // 0..56

    const float* pA = x + (bm + lm) * I_ + lk;
    const float* pB = W + (bn + lm) * I_ + lk;

    float acc[4][8] = {};

    float4 a0 = __ldg((const float4*)(pA + k_lo));
    float4 a1 = __ldg((const float4*)(pA + k_lo + 4));
    float4 b0 = __ldg((const float4*)(pB + k_lo));
    float4 b1 = __ldg((const float4*)(pB + k_lo + 4));

    for (int k0 = k_lo; k0 < k_hi; k0 += GBK) {
        sA[lk + 0][lm] = a0.x; sA[lk + 1][lm] = a0.y; sA[lk + 2][lm] = a0.z; sA[lk + 3][lm] = a0.w;
        sA[lk + 4][lm] = a1.x; sA[lk + 5][lm] = a1.y; sA[lk + 6][lm] = a1.z; sA[lk + 7][lm] = a1.w;
        sB[lk + 0][lm] = b0.x; sB[lk + 1][lm] = b0.y; sB[lk + 2][lm] = b0.z; sB[lk + 3][lm] = b0.w;
        sB[lk + 4][lm] = b1.x; sB[lk + 5][lm] = b1.y; sB[lk + 6][lm] = b1.z; sB[lk + 7][lm] = b1.w;
        __syncthreads();

        int kn = k0 + GBK;
        if (kn < k_hi) {
            a0 = __ldg((const float4*)(pA + kn));
            a1 = __ldg((const float4*)(pA + kn + 4));
            b0 = __ldg((const float4*)(pB + kn));
            b1 = __ldg((const float4*)(pB + kn + 4));
        }

        #pragma unroll
        for (int k = 0; k < GBK; k++) {
            float4 av  = *reinterpret_cast<const float4*>(&sA[k][tm]);
            float4 bv0 = *reinterpret_cast<const float4*>(&sB[k][tn]);
            float4 bv1 = *reinterpret_cast<const float4*>(&sB[k][tn + 4]);
            float a[4] = {av.x, av.y, av.z, av.w};
            float b[8] = {bv0.x, bv0.y, bv0.z, bv0.w, bv1.x, bv1.y, bv1.z, bv1.w};
            #pragma unroll
            for (int i = 0; i < 4; i++)
                #pragma unroll
                for (int j = 0; j < 8; j++)
                    acc[i][j] = fmaf(a[i], b[j], acc[i][j]);
        }
        __syncthreads();
    }

    float* out = g_part[z];
    #pragma unroll
    for (int i = 0; i < 4; i++) {
        float4 r0 = make_float4(acc[i][0], acc[i][1], acc[i][2], acc[i][3]);
        float4 r1 = make_float4(acc[i][4], acc[i][5], acc[i][6], acc[i][7]);
        float* row = out + (size_t)(bm + tm + i) * SIXH + bn + tn;
        *reinterpret_cast<float4*>(row)     = r0;
        *reinterpret_cast<float4*>(row + 4) = r1;
    }
}

// ---------------- Kernel 2: gate transforms + n.q reduction (fused) ----------------
// One block per batch b, 512 threads (one per h). gate order: ig,fg,og,q,k,v.
__global__ __launch_bounds__(512) void gate_kernel(
    const float* __restrict__ m_prev,
    const float* __restrict__ n_prev,
    const float* __restrict__ bias,
    float* __restrict__ out_m,
    float* __restrict__ out_n)
{
    const int b = blockIdx.x;
    const int h = threadIdx.x;
    const int base = b * SIXH;

    float g[6];
    #pragma unroll
    for (int gi = 0; gi < 6; gi++) {
        int off = base + gi * H_ + h;
        g[gi] = g_part[0][off] + g_part[1][off] + g_part[2][off] + bias[gi * H_ + h];
    }
    float ig = g[0], fg = g[1], og = g[2], qv = g[3], kk = g[4], vv = g[5];

    const int idx = b * H_ + h;
    float mp = m_prev[idx];
    float mt = fmaxf(fg + mp, ig);
    float it = expf(ig - mt);
    float ft = expf(fg + mp - mt);
    float kt = 0.04419417382415922f * kk;   // 1/sqrt(512)
    float nt = ft * n_prev[idx] + it * kt;

    out_m[idx] = mt;
    out_n[idx] = nt;
    g_f[idx]   = ft;
    g_add[idx] = it * vv * kt;
    g_o[idx]   = 1.0f / (1.0f + expf(-og));
    g_q[idx]   = qv;

    // deterministic block reduce of nt*qv over 512 threads
    float s = nt * qv;
    #pragma unroll
    for (int off = 16; off; off >>= 1) s += __shfl_xor_sync(0xffffffffu, s, off);

    __shared__ float red[16];
    int w = threadIdx.x >> 5, lane = threadIdx.x & 31;
    if (lane == 0) red[w] = s;
    __syncthreads();
    if (threadIdx.x == 0) {
        float tsum = 0.f;
        #pragma unroll
        for (int i = 0; i < 16; i++) tsum += red[i];
        g_denom[b] = fmaxf(fabsf(tsum), 1e-6f);
    }
}

// ---------------- Kernel 3: C_t update + readout + h_t ----------------
// One warp per (b,i) row of 512 floats; 8 warps per block; q[b] staged in smem.
// C_prev / out_C are touch-once streams -> evict-first (ldcs/stcs).
__global__ __launch_bounds__(256) void cmain_kernel(
    const float* __restrict__ C_prev,
    float* __restrict__ out_C,
    float* __restrict__ out_h)
{
    __shared__ float sq[H_];
    const int b = blockIdx.x >> 6;            // 64 blocks per batch
    const int row0 = (blockIdx.x & 63) * 8;

    const float* q = g_q + b * H_;
    for (int h = threadIdx.x; h < H_; h += 256) sq[h] = q[h];
    __syncthreads();

    const int w = threadIdx.x >> 5;
    const int lane = threadIdx.x & 31;
    const int i = row0 + w;
    const int bi = b * H_ + i;

    const float f   = g_f[bi];
    const float add = g_add[bi];

    const float4* Cp = reinterpret_cast<const float4*>(C_prev) + (size_t)bi * (H_ / 4);
    float4*       Co = reinterpret_cast<float4*>(out_C)        + (size_t)bi * (H_ / 4);
    const float4* q4 = reinterpret_cast<const float4*>(sq);

    float4 c[4];
    #pragma unroll
    for (int t = 0; t < 4; t++) c[t] = __ldcs(Cp + lane + t * 32);

    float acc = 0.f;
    #pragma unroll
    for (int t = 0; t < 4; t++) {
        int j4 = lane + t * 32;
        float4 r;
        r.x = fmaf(f, c[t].x, add);
        r.y = fmaf(f, c[t].y, add);
        r.z = fmaf(f, c[t].z, add);
        r.w = fmaf(f, c[t].w, add);
        __stcs(Co + j4, r);
        float4 qq = q4[j4];
        acc += r.x * qq.x + r.y * qq.y + r.z * qq.z + r.w * qq.w;
    }

    #pragma unroll
    for (int off = 16; off; off >>= 1) acc += __shfl_xor_sync(0xffffffffu, acc, off);

    if (lane == 0)
        out_h[bi] = g_o[bi] * acc / g_denom[b];
}

// ---------------- launch ----------------
extern "C" void kernel_launch(void* const* d_in, const int* in_sizes, int n_in,
                              void* d_out, int out_size)
{
    const float* x      = (const float*)d_in[0];
    // d_in[1] = h_prev (unused by the reference)
    const float* C_prev = (const float*)d_in[2];
    const float* m_prev = (const float*)d_in[3];
    const float* n_prev = (const float*)d_in[4];
    const float* W      = (const float*)d_in[5];
    const float* bias   = (const float*)d_in[6];

    float* out   = (float*)d_out;
    float* out_h = out;                       // [B,H]
    float* out_C = out + BH;                  // [B,H,H]
    float* out_m = out + BH + CSZ;            // [B,H]
    float* out_n = out + BH + CSZ + BH;       // [B,H]

    dim3 ggrid(SIXH / GBN, B_ / GBM, 3);      // (48, 2, 3) = 288 blocks
    gemm_kernel<<<ggrid, 128>>>(x, W);

    gate_kernel<<<B_, 512>>>(m_prev, n_prev, bias, out_m, out_n);

    cmain_kernel<<<B_ * 64, 256>>>(C_prev, out_C, out_h);
}